// round 9
// baseline (speedup 1.0000x reference)
#include <cuda_runtime.h>
#include <cuda_bf16.h>
#include <cstdint>

// ---------------------------------------------------------------------------
// Problem constants
// ---------------------------------------------------------------------------
#define B_ROWS   16384
#define D_DIM    2048
#define L_LAYERS 3
#define E_EXP    8
#define NCOL     (L_LAYERS * 1024)   // 3072 interleaved U/V columns (all layers)
#define NEXP     (L_LAYERS * E_EXP)  // 24

// GEMM tiling (R5 config): 128x128 tile, 4 warps (2m x 2n), 64x64 warp tile,
// 3 stages, 2 CTAs/SM.
#define BM 128
#define BN 128
#define KB 64                         // bf16 per k-step (128 B rows)
#define STAGES 3
#define KSTEPS (D_DIM / KB)           // 32
#define NSTEPS (3 * KSTEPS)           // 96: phases hh, lh, hl
#define A_BYTES (BM * 128)            // 16 KB
#define B_BYTES (BN * 128)            // 16 KB
#define STAGE_BYTES (A_BYTES + B_BYTES)      // 32 KB
#define SMEM_TOTAL (STAGES * STAGE_BYTES)    // 96 KB -> 2 CTAs/SM

// ---------------------------------------------------------------------------
// Device scratch (static)
// ---------------------------------------------------------------------------
__device__ __nv_bfloat16 g_Ahi[(size_t)B_ROWS * D_DIM];
__device__ __nv_bfloat16 g_Alo[(size_t)B_ROWS * D_DIM];
__device__ __nv_bfloat16 g_Bhi[(size_t)NCOL * D_DIM];
__device__ __nv_bfloat16 g_Blo[(size_t)NCOL * D_DIM];
__device__ float         g_e0[(size_t)B_ROWS * NEXP];
__device__ float         g_logit[(size_t)B_ROWS * NEXP];
__device__ float         g_c[B_ROWS];

// ---------------------------------------------------------------------------
// Helpers
// ---------------------------------------------------------------------------
__device__ __forceinline__ uint32_t smem_u32(const void* p) {
    uint32_t a;
    asm("{ .reg .u64 t; cvta.to.shared.u64 t, %1; cvt.u32.u64 %0, t; }"
        : "=r"(a) : "l"(p));
    return a;
}
__device__ __forceinline__ uint32_t swz(uint32_t off) {        // SW128
    return off ^ ((off >> 3) & 0x70);
}
__device__ __forceinline__ void cpa16(uint32_t dst, const void* src) {
    asm volatile("cp.async.cg.shared.global [%0], [%1], 16;"
                 :: "r"(dst), "l"(src) : "memory");
}
__device__ __forceinline__ void cpa_commit() {
    asm volatile("cp.async.commit_group;" ::: "memory");
}
__device__ __forceinline__ void cpa_wait1() {
    asm volatile("cp.async.wait_group 1;" ::: "memory");
}
__device__ __forceinline__ void ldsm_x4(uint32_t* r, uint32_t addr) {
    asm volatile("ldmatrix.sync.aligned.m8n8.x4.shared.b16 {%0,%1,%2,%3}, [%4];"
                 : "=r"(r[0]), "=r"(r[1]), "=r"(r[2]), "=r"(r[3]) : "r"(addr));
}
__device__ __forceinline__ void mma16816(float* d, const uint32_t* a,
                                         uint32_t b0, uint32_t b1) {
    asm volatile(
        "mma.sync.aligned.m16n8k16.row.col.f32.bf16.bf16.f32 "
        "{%0,%1,%2,%3}, {%4,%5,%6,%7}, {%8,%9}, {%0,%1,%2,%3};"
        : "+f"(d[0]), "+f"(d[1]), "+f"(d[2]), "+f"(d[3])
        : "r"(a[0]), "r"(a[1]), "r"(a[2]), "r"(a[3]), "r"(b0), "r"(b1));
}

// ---------------------------------------------------------------------------
// Merged prep kernel. Blocks [0, NCOL): weight split (U,V)->Bhi/Blo.
// Blocks [NCOL, NCOL+128): gate logits + X0 hi/lo split.
// Independent work, one launch -> concurrent execution.
// ---------------------------------------------------------------------------
#define GL_BM 128
#define GL_BK 64
__global__ __launch_bounds__(256) void prep_all(
    const float* __restrict__ U, const float* __restrict__ V,
    const float* __restrict__ X0, const float* __restrict__ Wg)
{
    if (blockIdx.x < NCOL) {
        // ---- weight split: one block per interleaved column ----
        const int row = blockIdx.x;
        const int l = row >> 10, c = row & 1023;
        const int e = c >> 7, i = c & 127, r = i >> 1, uv = i & 1;
        const float* src = (uv ? V : U)
                         + (((size_t)(l * E_EXP + e)) * 64 + r) * D_DIM;
        const size_t dst = (size_t)row * D_DIM;
        const int k = threadIdx.x * 8;
        float4 a = *reinterpret_cast<const float4*>(src + k);
        float4 b = *reinterpret_cast<const float4*>(src + k + 4);
        float v[8] = {a.x, a.y, a.z, a.w, b.x, b.y, b.z, b.w};
        __nv_bfloat16 hi[8], lo[8];
#pragma unroll
        for (int j = 0; j < 8; j++) {
            hi[j] = __float2bfloat16(v[j]);
            lo[j] = __float2bfloat16(v[j] - __bfloat162float(hi[j]));
        }
        *reinterpret_cast<uint4*>(&g_Bhi[dst + k]) = *reinterpret_cast<uint4*>(hi);
        *reinterpret_cast<uint4*>(&g_Blo[dst + k]) = *reinterpret_cast<uint4*>(lo);
        return;
    }

    // ---- gate logits + X0 split ----
    __shared__ float As[GL_BK][GL_BM + 1];
    __shared__ float Ws[GL_BK][36];
    const int tid = threadIdx.x;
    const int m0 = (blockIdx.x - NCOL) * GL_BM;
    const int row = tid >> 1;
    const int ch = (tid & 1) * 12;
    float acc[12];
#pragma unroll
    for (int j = 0; j < 12; j++) acc[j] = 0.f;

    for (int kc = 0; kc < D_DIM; kc += GL_BK) {
#pragma unroll
        for (int i = 0; i < 8; i++) {
            const int idx = i * 256 + tid;
            const int r = idx >> 4, c4 = (idx & 15) * 4;
            const size_t gidx = (size_t)(m0 + r) * D_DIM + kc + c4;
            float4 v = *reinterpret_cast<const float4*>(X0 + gidx);
            As[c4 + 0][r] = v.x; As[c4 + 1][r] = v.y;
            As[c4 + 2][r] = v.z; As[c4 + 3][r] = v.w;
            float vv[4] = {v.x, v.y, v.z, v.w};
            __nv_bfloat16 hi[4], lo[4];
#pragma unroll
            for (int q = 0; q < 4; q++) {
                hi[q] = __float2bfloat16(vv[q]);
                lo[q] = __float2bfloat16(vv[q] - __bfloat162float(hi[q]));
            }
            *reinterpret_cast<uint2*>(&g_Ahi[gidx]) = *reinterpret_cast<uint2*>(hi);
            *reinterpret_cast<uint2*>(&g_Alo[gidx]) = *reinterpret_cast<uint2*>(lo);
        }
#pragma unroll
        for (int i = 0; i < 2; i++) {
            const int idx = i * 256 + tid;
            if (idx < 384) {
                const int r = idx >> 4, c4 = (idx & 15) * 4;
                float4 v = *reinterpret_cast<const float4*>(
                    Wg + (size_t)r * D_DIM + kc + c4);
                Ws[c4 + 0][r] = v.x; Ws[c4 + 1][r] = v.y;
                Ws[c4 + 2][r] = v.z; Ws[c4 + 3][r] = v.w;
            }
        }
        __syncthreads();
#pragma unroll 8
        for (int kk = 0; kk < GL_BK; kk++) {
            const float a = As[kk][row];
            float4 w0 = *reinterpret_cast<float4*>(&Ws[kk][ch]);
            float4 w1 = *reinterpret_cast<float4*>(&Ws[kk][ch + 4]);
            float4 w2 = *reinterpret_cast<float4*>(&Ws[kk][ch + 8]);
            acc[0] += a * w0.x; acc[1] += a * w0.y;
            acc[2] += a * w0.z; acc[3] += a * w0.w;
            acc[4] += a * w1.x; acc[5] += a * w1.y;
            acc[6] += a * w1.z; acc[7] += a * w1.w;
            acc[8] += a * w2.x; acc[9] += a * w2.y;
            acc[10] += a * w2.z; acc[11] += a * w2.w;
        }
        __syncthreads();
    }
    float* dst = g_logit + (size_t)(m0 + row) * NEXP + ch;
#pragma unroll
    for (int j = 0; j < 12; j++) dst[j] = acc[j];
}

// ---------------------------------------------------------------------------
// HMMA GEMM with fused expert-sum epilogue (R5 config).
// Grid (128 m-tiles, 24 experts): x fastest => consecutive CTAs share the
// same expert B band (L2 residency). 128 threads = 4 warps (2m x 2n),
// warp tile 64x64, 2 CTAs/SM.
// ---------------------------------------------------------------------------
__global__ __launch_bounds__(128, 2) void gemm_hmma()
{
    extern __shared__ char smem[];
    const uint32_t sb = smem_u32(smem);
    const int tid = threadIdx.x;
    const int lane = tid & 31, warp = tid >> 5;
    const int wm = warp & 1, wn = warp >> 1;     // 2m x 2n
    const int nt = blockIdx.y;                    // 0..23 (global expert)
    const int m0 = blockIdx.x * BM;
    const size_t brow0 = (size_t)nt * BN;

    float acc[4][8][4];
#pragma unroll
    for (int mi = 0; mi < 4; mi++)
#pragma unroll
        for (int ni = 0; ni < 8; ni++)
#pragma unroll
            for (int j = 0; j < 4; j++) acc[mi][ni][j] = 0.f;

    auto load_stage = [&](int step) {
        if (step < NSTEPS) {
            const int p = (step >= 2 * KSTEPS) ? 2 : (step >= KSTEPS ? 1 : 0);
            const int k0 = (step - p * KSTEPS) * KB;
            const __nv_bfloat16* Asrc = (p == 1) ? g_Alo : g_Ahi;
            const __nv_bfloat16* Bsrc = (p == 2) ? g_Blo : g_Bhi;
            const uint32_t a_base = sb + (step % STAGES) * STAGE_BYTES;
            const uint32_t b_base = a_base + A_BYTES;
#pragma unroll
            for (int i = 0; i < 8; i++) {
                const int idx = i * 128 + tid;
                const int r = idx >> 3, c = idx & 7;
                cpa16(a_base + swz(r * 128 + c * 16),
                      Asrc + (size_t)(m0 + r) * D_DIM + k0 + c * 8);
            }
#pragma unroll
            for (int i = 0; i < 8; i++) {
                const int idx = i * 128 + tid;
                const int r = idx >> 3, c = idx & 7;
                cpa16(b_base + swz(r * 128 + c * 16),
                      Bsrc + (brow0 + r) * D_DIM + k0 + c * 8);
            }
        }
        cpa_commit();
    };

    load_stage(0); load_stage(1);

    const int arow = wm * 64 + (lane & 15);
    const int brow = wn * 64 + (lane & 15);
    const int khalf = (lane >> 4) * 16;

    for (int step = 0; step < NSTEPS; ++step) {
        cpa_wait1();
        __syncthreads();
        load_stage(step + 2);

        const uint32_t a_base = sb + (step % STAGES) * STAGE_BYTES;
        const uint32_t b_base = a_base + A_BYTES;
#pragma unroll
        for (int k16 = 0; k16 < 4; k16++) {
            const int kb = k16 * 32 + khalf;
            uint32_t a[4][4], bb[4][4];
#pragma unroll
            for (int mi = 0; mi < 4; mi++)
                ldsm_x4(a[mi], a_base + swz((arow + mi * 16) * 128 + kb));
#pragma unroll
            for (int nj = 0; nj < 4; nj++)
                ldsm_x4(bb[nj], b_base + swz((brow + nj * 16) * 128 + kb));
#pragma unroll
            for (int mi = 0; mi < 4; mi++)
#pragma unroll
                for (int ni = 0; ni < 8; ni++)
                    mma16816(acc[mi][ni], a[mi],
                             bb[ni >> 1][ni & 1], bb[ni >> 1][(ni & 1) + 2]);
        }
    }

    // ---- Fused epilogue: pair products -> per-row expert sum ----
    __syncthreads();
    float* esum = reinterpret_cast<float*>(smem);   // [128]
    esum[tid] = 0.f;
    __syncthreads();

#pragma unroll
    for (int mi = 0; mi < 4; mi++) {
        float pl = 0.f, ph = 0.f;
#pragma unroll
        for (int ni = 0; ni < 8; ni++) {
            pl += acc[mi][ni][0] * acc[mi][ni][1];
            ph += acc[mi][ni][2] * acc[mi][ni][3];
        }
        pl += __shfl_xor_sync(0xffffffffu, pl, 1);
        pl += __shfl_xor_sync(0xffffffffu, pl, 2);
        ph += __shfl_xor_sync(0xffffffffu, ph, 1);
        ph += __shfl_xor_sync(0xffffffffu, ph, 2);
        if ((lane & 3) == 0) {
            const int r = wm * 64 + mi * 16 + (lane >> 2);
            atomicAdd(&esum[r], pl);
            atomicAdd(&esum[r + 8], ph);
        }
    }
    __syncthreads();
    g_e0[(size_t)(m0 + tid) * NEXP + nt] = esum[tid];
}

// ---------------------------------------------------------------------------
// compute_c: per-row scalar recurrence (one thread per row).
// ---------------------------------------------------------------------------
__global__ __launch_bounds__(256) void compute_c(const float* __restrict__ bg)
{
    const int b = blockIdx.x * 256 + threadIdx.x;
    const float* e0 = g_e0 + (size_t)b * NEXP;
    const float* lg = g_logit + (size_t)b * NEXP;
    float c = 1.f;
#pragma unroll
    for (int l = 0; l < L_LAYERS; l++) {
        const int base = l * E_EXP;
        float logit[E_EXP], mx = -1e30f;
#pragma unroll
        for (int e = 0; e < E_EXP; e++) {
            logit[e] = c * lg[base + e] + bg[base + e];
            mx = fmaxf(mx, logit[e]);
        }
        float se = 0.f, acc = 0.f;
#pragma unroll
        for (int e = 0; e < E_EXP; e++) {
            const float ge = expf(logit[e] - mx);
            se += ge;
            acc += ge * e0[base + e];
        }
        c += c * c * (acc / se);
    }
    g_c[b] = c;
}

// ---------------------------------------------------------------------------
// scale: out = c[row] * X0, flat float4 streaming.
// ---------------------------------------------------------------------------
__global__ __launch_bounds__(256) void scale_out(
    const float* __restrict__ X0, float* __restrict__ out)
{
    const size_t j0 = ((size_t)blockIdx.x * 256 + threadIdx.x) * 8;  // float4 idx
    const float4* x4 = reinterpret_cast<const float4*>(X0);
    float4* o4 = reinterpret_cast<float4*>(out);
#pragma unroll
    for (int i = 0; i < 8; i++) {
        const size_t j = j0 + i;
        const float c = g_c[j >> 9];         // 512 float4 per row
        float4 x = x4[j];
        x.x *= c; x.y *= c; x.z *= c; x.w *= c;
        o4[j] = x;
    }
}

// ---------------------------------------------------------------------------
// Launch
// ---------------------------------------------------------------------------
extern "C" void kernel_launch(void* const* d_in, const int* in_sizes, int n_in,
                              void* d_out, int out_size) {
    const float* X0 = (const float*)d_in[0];
    const float* U  = (const float*)d_in[1];
    const float* V  = (const float*)d_in[2];
    const float* Wg = (const float*)d_in[3];
    const float* bg = (const float*)d_in[4];
    float* out = (float*)d_out;

    cudaFuncSetAttribute(gemm_hmma, cudaFuncAttributeMaxDynamicSharedMemorySize,
                         SMEM_TOTAL);

    prep_all<<<NCOL + B_ROWS / GL_BM, 256>>>(U, V, X0, Wg);
    gemm_hmma<<<dim3(B_ROWS / BM, NEXP), 128, SMEM_TOTAL>>>();
    compute_c<<<B_ROWS / 256, 256>>>(bg);
    scale_out<<<(B_ROWS * D_DIM) / (256 * 32), 256>>>(X0, out);
}

// round 10
// speedup vs baseline: 1.0251x; 1.0251x over previous
#include <cuda_runtime.h>
#include <cuda_bf16.h>
#include <cstdint>

// ---------------------------------------------------------------------------
// Problem constants
// ---------------------------------------------------------------------------
#define B_ROWS   16384
#define D_DIM    2048
#define L_LAYERS 3
#define E_EXP    8
#define NCOL     (L_LAYERS * 1024)   // 3072 interleaved U/V columns (all layers)
#define NEXP     (L_LAYERS * E_EXP)  // 24

// GEMM tiling (R5 config): 128x128 tile, 4 warps (2m x 2n), 64x64 warp tile,
// 3 stages, 2 CTAs/SM.
#define BM 128
#define BN 128
#define KB 64                         // bf16 per k-step (128 B rows)
#define STAGES 3
#define KSTEPS (D_DIM / KB)           // 32
#define NSTEPS (3 * KSTEPS)           // 96: phases hh, lh, hl
#define A_BYTES (BM * 128)            // 16 KB
#define B_BYTES (BN * 128)            // 16 KB
#define STAGE_BYTES (A_BYTES + B_BYTES)      // 32 KB
#define SMEM_TOTAL (STAGES * STAGE_BYTES)    // 96 KB -> 2 CTAs/SM

// ---------------------------------------------------------------------------
// Device scratch (static)
// ---------------------------------------------------------------------------
__device__ __nv_bfloat16 g_Ahi[(size_t)B_ROWS * D_DIM];
__device__ __nv_bfloat16 g_Alo[(size_t)B_ROWS * D_DIM];
__device__ __nv_bfloat16 g_Bhi[(size_t)NCOL * D_DIM];
__device__ __nv_bfloat16 g_Blo[(size_t)NCOL * D_DIM];
__device__ float         g_e0[(size_t)B_ROWS * NEXP];
__device__ float         g_logit[(size_t)B_ROWS * NEXP];
__device__ float         g_c[B_ROWS];

// ---------------------------------------------------------------------------
// Helpers
// ---------------------------------------------------------------------------
__device__ __forceinline__ uint32_t smem_u32(const void* p) {
    uint32_t a;
    asm("{ .reg .u64 t; cvta.to.shared.u64 t, %1; cvt.u32.u64 %0, t; }"
        : "=r"(a) : "l"(p));
    return a;
}
__device__ __forceinline__ uint32_t swz(uint32_t off) {        // SW128
    return off ^ ((off >> 3) & 0x70);
}
__device__ __forceinline__ void cpa16(uint32_t dst, const void* src) {
    asm volatile("cp.async.cg.shared.global [%0], [%1], 16;"
                 :: "r"(dst), "l"(src) : "memory");
}
__device__ __forceinline__ void cpa_commit() {
    asm volatile("cp.async.commit_group;" ::: "memory");
}
__device__ __forceinline__ void cpa_wait1() {
    asm volatile("cp.async.wait_group 1;" ::: "memory");
}
__device__ __forceinline__ void ldsm_x4(uint32_t* r, uint32_t addr) {
    asm volatile("ldmatrix.sync.aligned.m8n8.x4.shared.b16 {%0,%1,%2,%3}, [%4];"
                 : "=r"(r[0]), "=r"(r[1]), "=r"(r[2]), "=r"(r[3]) : "r"(addr));
}
__device__ __forceinline__ void mma16816(float* d, const uint32_t* a,
                                         uint32_t b0, uint32_t b1) {
    asm volatile(
        "mma.sync.aligned.m16n8k16.row.col.f32.bf16.bf16.f32 "
        "{%0,%1,%2,%3}, {%4,%5,%6,%7}, {%8,%9}, {%0,%1,%2,%3};"
        : "+f"(d[0]), "+f"(d[1]), "+f"(d[2]), "+f"(d[3])
        : "r"(a[0]), "r"(a[1]), "r"(a[2]), "r"(a[3]), "r"(b0), "r"(b1));
}

// ---------------------------------------------------------------------------
// Merged prep kernel. Blocks [0, NCOL): weight split (U,V)->Bhi/Blo.
// Blocks [NCOL, NCOL+128): gate logits + X0 hi/lo split.
// ---------------------------------------------------------------------------
#define GL_BM 128
#define GL_BK 64
__global__ __launch_bounds__(256) void prep_all(
    const float* __restrict__ U, const float* __restrict__ V,
    const float* __restrict__ X0, const float* __restrict__ Wg)
{
    if (blockIdx.x < NCOL) {
        // ---- weight split: one block per interleaved column ----
        const int row = blockIdx.x;
        const int l = row >> 10, c = row & 1023;
        const int e = c >> 7, i = c & 127, r = i >> 1, uv = i & 1;
        const float* src = (uv ? V : U)
                         + (((size_t)(l * E_EXP + e)) * 64 + r) * D_DIM;
        const size_t dst = (size_t)row * D_DIM;
        const int k = threadIdx.x * 8;
        float4 a = *reinterpret_cast<const float4*>(src + k);
        float4 b = *reinterpret_cast<const float4*>(src + k + 4);
        float v[8] = {a.x, a.y, a.z, a.w, b.x, b.y, b.z, b.w};
        __nv_bfloat16 hi[8], lo[8];
#pragma unroll
        for (int j = 0; j < 8; j++) {
            hi[j] = __float2bfloat16(v[j]);
            lo[j] = __float2bfloat16(v[j] - __bfloat162float(hi[j]));
        }
        *reinterpret_cast<uint4*>(&g_Bhi[dst + k]) = *reinterpret_cast<uint4*>(hi);
        *reinterpret_cast<uint4*>(&g_Blo[dst + k]) = *reinterpret_cast<uint4*>(lo);
        return;
    }

    // ---- gate logits + X0 split ----
    __shared__ float As[GL_BK][GL_BM + 1];
    __shared__ float Ws[GL_BK][36];
    const int tid = threadIdx.x;
    const int m0 = (blockIdx.x - NCOL) * GL_BM;
    const int row = tid >> 1;
    const int ch = (tid & 1) * 12;
    float acc[12];
#pragma unroll
    for (int j = 0; j < 12; j++) acc[j] = 0.f;

    for (int kc = 0; kc < D_DIM; kc += GL_BK) {
#pragma unroll
        for (int i = 0; i < 8; i++) {
            const int idx = i * 256 + tid;
            const int r = idx >> 4, c4 = (idx & 15) * 4;
            const size_t gidx = (size_t)(m0 + r) * D_DIM + kc + c4;
            float4 v = *reinterpret_cast<const float4*>(X0 + gidx);
            As[c4 + 0][r] = v.x; As[c4 + 1][r] = v.y;
            As[c4 + 2][r] = v.z; As[c4 + 3][r] = v.w;
            float vv[4] = {v.x, v.y, v.z, v.w};
            __nv_bfloat16 hi[4], lo[4];
#pragma unroll
            for (int q = 0; q < 4; q++) {
                hi[q] = __float2bfloat16(vv[q]);
                lo[q] = __float2bfloat16(vv[q] - __bfloat162float(hi[q]));
            }
            *reinterpret_cast<uint2*>(&g_Ahi[gidx]) = *reinterpret_cast<uint2*>(hi);
            *reinterpret_cast<uint2*>(&g_Alo[gidx]) = *reinterpret_cast<uint2*>(lo);
        }
#pragma unroll
        for (int i = 0; i < 2; i++) {
            const int idx = i * 256 + tid;
            if (idx < 384) {
                const int r = idx >> 4, c4 = (idx & 15) * 4;
                float4 v = *reinterpret_cast<const float4*>(
                    Wg + (size_t)r * D_DIM + kc + c4);
                Ws[c4 + 0][r] = v.x; Ws[c4 + 1][r] = v.y;
                Ws[c4 + 2][r] = v.z; Ws[c4 + 3][r] = v.w;
            }
        }
        __syncthreads();
#pragma unroll 8
        for (int kk = 0; kk < GL_BK; kk++) {
            const float a = As[kk][row];
            float4 w0 = *reinterpret_cast<float4*>(&Ws[kk][ch]);
            float4 w1 = *reinterpret_cast<float4*>(&Ws[kk][ch + 4]);
            float4 w2 = *reinterpret_cast<float4*>(&Ws[kk][ch + 8]);
            acc[0] += a * w0.x; acc[1] += a * w0.y;
            acc[2] += a * w0.z; acc[3] += a * w0.w;
            acc[4] += a * w1.x; acc[5] += a * w1.y;
            acc[6] += a * w1.z; acc[7] += a * w1.w;
            acc[8] += a * w2.x; acc[9] += a * w2.y;
            acc[10] += a * w2.z; acc[11] += a * w2.w;
        }
        __syncthreads();
    }
    float* dst = g_logit + (size_t)(m0 + row) * NEXP + ch;
#pragma unroll
    for (int j = 0; j < 12; j++) dst[j] = acc[j];
}

// ---------------------------------------------------------------------------
// HMMA GEMM with fused expert-sum epilogue (R5 config, R5 grid order:
// x = expert (fast) so each wave shares A m-bands across all 24 experts).
// 128 threads = 4 warps (2m x 2n), warp tile 64x64, 2 CTAs/SM.
// ---------------------------------------------------------------------------
__global__ __launch_bounds__(128, 2) void gemm_hmma()
{
    extern __shared__ char smem[];
    const uint32_t sb = smem_u32(smem);
    const int tid = threadIdx.x;
    const int lane = tid & 31, warp = tid >> 5;
    const int wm = warp & 1, wn = warp >> 1;     // 2m x 2n
    const int nt = blockIdx.x;                    // 0..23 (global expert)
    const int m0 = blockIdx.y * BM;
    const size_t brow0 = (size_t)nt * BN;

    float acc[4][8][4];
#pragma unroll
    for (int mi = 0; mi < 4; mi++)
#pragma unroll
        for (int ni = 0; ni < 8; ni++)
#pragma unroll
            for (int j = 0; j < 4; j++) acc[mi][ni][j] = 0.f;

    auto load_stage = [&](int step) {
        if (step < NSTEPS) {
            const int p = (step >= 2 * KSTEPS) ? 2 : (step >= KSTEPS ? 1 : 0);
            const int k0 = (step - p * KSTEPS) * KB;
            const __nv_bfloat16* Asrc = (p == 1) ? g_Alo : g_Ahi;
            const __nv_bfloat16* Bsrc = (p == 2) ? g_Blo : g_Bhi;
            const uint32_t a_base = sb + (step % STAGES) * STAGE_BYTES;
            const uint32_t b_base = a_base + A_BYTES;
#pragma unroll
            for (int i = 0; i < 8; i++) {
                const int idx = i * 128 + tid;
                const int r = idx >> 3, c = idx & 7;
                cpa16(a_base + swz(r * 128 + c * 16),
                      Asrc + (size_t)(m0 + r) * D_DIM + k0 + c * 8);
            }
#pragma unroll
            for (int i = 0; i < 8; i++) {
                const int idx = i * 128 + tid;
                const int r = idx >> 3, c = idx & 7;
                cpa16(b_base + swz(r * 128 + c * 16),
                      Bsrc + (brow0 + r) * D_DIM + k0 + c * 8);
            }
        }
        cpa_commit();
    };

    load_stage(0); load_stage(1);

    const int arow = wm * 64 + (lane & 15);
    const int brow = wn * 64 + (lane & 15);
    const int khalf = (lane >> 4) * 16;

    for (int step = 0; step < NSTEPS; ++step) {
        cpa_wait1();
        __syncthreads();
        load_stage(step + 2);

        const uint32_t a_base = sb + (step % STAGES) * STAGE_BYTES;
        const uint32_t b_base = a_base + A_BYTES;
#pragma unroll
        for (int k16 = 0; k16 < 4; k16++) {
            const int kb = k16 * 32 + khalf;
            uint32_t a[4][4], bb[4][4];
#pragma unroll
            for (int mi = 0; mi < 4; mi++)
                ldsm_x4(a[mi], a_base + swz((arow + mi * 16) * 128 + kb));
#pragma unroll
            for (int nj = 0; nj < 4; nj++)
                ldsm_x4(bb[nj], b_base + swz((brow + nj * 16) * 128 + kb));
#pragma unroll
            for (int mi = 0; mi < 4; mi++)
#pragma unroll
                for (int ni = 0; ni < 8; ni++)
                    mma16816(acc[mi][ni], a[mi],
                             bb[ni >> 1][ni & 1], bb[ni >> 1][(ni & 1) + 2]);
        }
    }

    // ---- Fused epilogue: pair products -> per-row expert sum ----
    __syncthreads();
    float* esum = reinterpret_cast<float*>(smem);   // [128]
    esum[tid] = 0.f;
    __syncthreads();

#pragma unroll
    for (int mi = 0; mi < 4; mi++) {
        float pl = 0.f, ph = 0.f;
#pragma unroll
        for (int ni = 0; ni < 8; ni++) {
            pl += acc[mi][ni][0] * acc[mi][ni][1];
            ph += acc[mi][ni][2] * acc[mi][ni][3];
        }
        pl += __shfl_xor_sync(0xffffffffu, pl, 1);
        pl += __shfl_xor_sync(0xffffffffu, pl, 2);
        ph += __shfl_xor_sync(0xffffffffu, ph, 1);
        ph += __shfl_xor_sync(0xffffffffu, ph, 2);
        if ((lane & 3) == 0) {
            const int r = wm * 64 + mi * 16 + (lane >> 2);
            atomicAdd(&esum[r], pl);
            atomicAdd(&esum[r + 8], ph);
        }
    }
    __syncthreads();
    g_e0[(size_t)(m0 + tid) * NEXP + nt] = esum[tid];
}

// ---------------------------------------------------------------------------
// compute_c: per-row scalar recurrence (one thread per row).
// ---------------------------------------------------------------------------
__global__ __launch_bounds__(256) void compute_c(const float* __restrict__ bg)
{
    const int b = blockIdx.x * 256 + threadIdx.x;
    const float* e0 = g_e0 + (size_t)b * NEXP;
    const float* lg = g_logit + (size_t)b * NEXP;
    float c = 1.f;
#pragma unroll
    for (int l = 0; l < L_LAYERS; l++) {
        const int base = l * E_EXP;
        float logit[E_EXP], mx = -1e30f;
#pragma unroll
        for (int e = 0; e < E_EXP; e++) {
            logit[e] = c * lg[base + e] + bg[base + e];
            mx = fmaxf(mx, logit[e]);
        }
        float se = 0.f, acc = 0.f;
#pragma unroll
        for (int e = 0; e < E_EXP; e++) {
            const float ge = expf(logit[e] - mx);
            se += ge;
            acc += ge * e0[base + e];
        }
        c += c * c * (acc / se);
    }
    g_c[b] = c;
}

// ---------------------------------------------------------------------------
// scale: out = c[row] * X0. Coalesced: one float4 per lane per iteration,
// grid-stride. 512 float4 per row -> per-warp c lookup is a broadcast.
// ---------------------------------------------------------------------------
#define SC_BLOCKS 4096
__global__ __launch_bounds__(256) void scale_out(
    const float* __restrict__ X0, float* __restrict__ out)
{
    const size_t total4 = (size_t)B_ROWS * D_DIM / 4;       // 8388608
    const size_t stride = (size_t)SC_BLOCKS * 256;           // 1048576
    size_t j = (size_t)blockIdx.x * 256 + threadIdx.x;
    const float4* x4 = reinterpret_cast<const float4*>(X0);
    float4* o4 = reinterpret_cast<float4*>(out);
#pragma unroll
    for (int i = 0; i < 8; i++, j += stride) {
        if (j < total4) {
            const float c = g_c[j >> 9];     // 512 float4 per row
            float4 x = x4[j];
            x.x *= c; x.y *= c; x.z *= c; x.w *= c;
            o4[j] = x;
        }
    }
}

// ---------------------------------------------------------------------------
// Launch
// ---------------------------------------------------------------------------
extern "C" void kernel_launch(void* const* d_in, const int* in_sizes, int n_in,
                              void* d_out, int out_size) {
    const float* X0 = (const float*)d_in[0];
    const float* U  = (const float*)d_in[1];
    const float* V  = (const float*)d_in[2];
    const float* Wg = (const float*)d_in[3];
    const float* bg = (const float*)d_in[4];
    float* out = (float*)d_out;

    cudaFuncSetAttribute(gemm_hmma, cudaFuncAttributeMaxDynamicSharedMemorySize,
                         SMEM_TOTAL);

    prep_all<<<NCOL + B_ROWS / GL_BM, 256>>>(U, V, X0, Wg);
    gemm_hmma<<<dim3(NEXP, B_ROWS / BM), 128, SMEM_TOTAL>>>();
    compute_c<<<B_ROWS / 256, 256>>>(bg);
    scale_out<<<SC_BLOCKS, 256>>>(X0, out);
}

// round 11
// speedup vs baseline: 1.0877x; 1.0611x over previous
#include <cuda_runtime.h>
#include <cuda_bf16.h>
#include <cstdint>

// ---------------------------------------------------------------------------
// Problem constants
// ---------------------------------------------------------------------------
#define B_ROWS   16384
#define D_DIM    2048
#define L_LAYERS 3
#define E_EXP    8
#define NCOL     (L_LAYERS * 1024)   // 3072 interleaved U/V columns (all layers)
#define NEXP     (L_LAYERS * E_EXP)  // 24

// GEMM tiling (R5 config): 128x128 tile, 4 warps (2m x 2n), 64x64 warp tile,
// 3 stages, 2 CTAs/SM.
#define BM 128
#define BN 128
#define KB 64                         // bf16 per k-step (128 B rows)
#define STAGES 3
#define KSTEPS (D_DIM / KB)           // 32
#define NSTEPS (3 * KSTEPS)           // 96: phases hh, lh, hl
#define A_BYTES (BM * 128)            // 16 KB
#define B_BYTES (BN * 128)            // 16 KB
#define STAGE_BYTES (A_BYTES + B_BYTES)      // 32 KB
#define SMEM_TOTAL (STAGES * STAGE_BYTES)    // 96 KB -> 2 CTAs/SM

// ---------------------------------------------------------------------------
// Device scratch (static)
// ---------------------------------------------------------------------------
__device__ __nv_bfloat16 g_Ahi[(size_t)B_ROWS * D_DIM];
__device__ __nv_bfloat16 g_Alo[(size_t)B_ROWS * D_DIM];
__device__ __nv_bfloat16 g_Bhi[(size_t)NCOL * D_DIM];
__device__ __nv_bfloat16 g_Blo[(size_t)NCOL * D_DIM];
__device__ float         g_e0[(size_t)B_ROWS * NEXP];
__device__ float         g_logit[(size_t)B_ROWS * NEXP];
__device__ float         g_c[B_ROWS];

// ---------------------------------------------------------------------------
// Helpers
// ---------------------------------------------------------------------------
__device__ __forceinline__ uint32_t smem_u32(const void* p) {
    uint32_t a;
    asm("{ .reg .u64 t; cvta.to.shared.u64 t, %1; cvt.u32.u64 %0, t; }"
        : "=r"(a) : "l"(p));
    return a;
}
__device__ __forceinline__ uint32_t swz(uint32_t off) {        // SW128
    return off ^ ((off >> 3) & 0x70);
}
__device__ __forceinline__ void cpa16(uint32_t dst, const void* src) {
    asm volatile("cp.async.cg.shared.global [%0], [%1], 16;"
                 :: "r"(dst), "l"(src) : "memory");
}
__device__ __forceinline__ void cpa_commit() {
    asm volatile("cp.async.commit_group;" ::: "memory");
}
__device__ __forceinline__ void cpa_wait1() {
    asm volatile("cp.async.wait_group 1;" ::: "memory");
}
__device__ __forceinline__ void ldsm_x4(uint32_t* r, uint32_t addr) {
    asm volatile("ldmatrix.sync.aligned.m8n8.x4.shared.b16 {%0,%1,%2,%3}, [%4];"
                 : "=r"(r[0]), "=r"(r[1]), "=r"(r[2]), "=r"(r[3]) : "r"(addr));
}
__device__ __forceinline__ void mma16816(float* d, const uint32_t* a,
                                         uint32_t b0, uint32_t b1) {
    asm volatile(
        "mma.sync.aligned.m16n8k16.row.col.f32.bf16.bf16.f32 "
        "{%0,%1,%2,%3}, {%4,%5,%6,%7}, {%8,%9}, {%0,%1,%2,%3};"
        : "+f"(d[0]), "+f"(d[1]), "+f"(d[2]), "+f"(d[3])
        : "r"(a[0]), "r"(a[1]), "r"(a[2]), "r"(a[3]), "r"(b0), "r"(b1));
}

// ---------------------------------------------------------------------------
// Weight prep: (U,V) fp32 -> interleaved-pair bf16 hi/lo, K-contiguous rows.
// ---------------------------------------------------------------------------
__global__ __launch_bounds__(256) void prep_weights(
    const float* __restrict__ U, const float* __restrict__ V)
{
    const int row = blockIdx.x;
    const int l = row >> 10, c = row & 1023;
    const int e = c >> 7, i = c & 127, r = i >> 1, uv = i & 1;
    const float* src = (uv ? V : U) + (((size_t)(l * E_EXP + e)) * 64 + r) * D_DIM;
    const size_t dst = (size_t)row * D_DIM;
    const int k = threadIdx.x * 8;
    float4 a = *reinterpret_cast<const float4*>(src + k);
    float4 b = *reinterpret_cast<const float4*>(src + k + 4);
    float v[8] = {a.x, a.y, a.z, a.w, b.x, b.y, b.z, b.w};
    __nv_bfloat16 hi[8], lo[8];
#pragma unroll
    for (int j = 0; j < 8; j++) {
        hi[j] = __float2bfloat16(v[j]);
        lo[j] = __float2bfloat16(v[j] - __bfloat162float(hi[j]));
    }
    *reinterpret_cast<uint4*>(&g_Bhi[dst + k]) = *reinterpret_cast<uint4*>(hi);
    *reinterpret_cast<uint4*>(&g_Blo[dst + k]) = *reinterpret_cast<uint4*>(lo);
}

// ---------------------------------------------------------------------------
// X0 split (streaming, 8192 independent blocks).
// ---------------------------------------------------------------------------
__global__ __launch_bounds__(256) void split_x0(const float* __restrict__ X0)
{
    const size_t base = ((size_t)blockIdx.x * 256 + threadIdx.x) * 16;
#pragma unroll
    for (int cidx = 0; cidx < 4; cidx++) {
        const size_t idx = base + cidx * 4;
        float4 v = *reinterpret_cast<const float4*>(X0 + idx);
        float vv[4] = {v.x, v.y, v.z, v.w};
        __nv_bfloat16 hi[4], lo[4];
#pragma unroll
        for (int j = 0; j < 4; j++) {
            hi[j] = __float2bfloat16(vv[j]);
            lo[j] = __float2bfloat16(vv[j] - __bfloat162float(hi[j]));
        }
        *reinterpret_cast<uint2*>(&g_Ahi[idx]) = *reinterpret_cast<uint2*>(hi);
        *reinterpret_cast<uint2*>(&g_Alo[idx]) = *reinterpret_cast<uint2*>(lo);
    }
}

// ---------------------------------------------------------------------------
// Gate logits: fp32 skinny GEMM, logit0[b, gl] = X0[b,:] . Wg[gl,:].
// ---------------------------------------------------------------------------
#define GL_BM 128
#define GL_BK 64
__global__ __launch_bounds__(256) void gate_logits(
    const float* __restrict__ X0, const float* __restrict__ Wg)
{
    __shared__ float As[GL_BK][GL_BM + 1];
    __shared__ float Ws[GL_BK][36];
    const int tid = threadIdx.x;
    const int m0 = blockIdx.x * GL_BM;
    const int row = tid >> 1;
    const int ch = (tid & 1) * 12;
    float acc[12];
#pragma unroll
    for (int j = 0; j < 12; j++) acc[j] = 0.f;

    for (int kc = 0; kc < D_DIM; kc += GL_BK) {
#pragma unroll
        for (int i = 0; i < 8; i++) {
            const int idx = i * 256 + tid;
            const int r = idx >> 4, c4 = (idx & 15) * 4;
            float4 v = *reinterpret_cast<const float4*>(
                X0 + (size_t)(m0 + r) * D_DIM + kc + c4);
            As[c4 + 0][r] = v.x; As[c4 + 1][r] = v.y;
            As[c4 + 2][r] = v.z; As[c4 + 3][r] = v.w;
        }
#pragma unroll
        for (int i = 0; i < 2; i++) {
            const int idx = i * 256 + tid;
            if (idx < 384) {
                const int r = idx >> 4, c4 = (idx & 15) * 4;
                float4 v = *reinterpret_cast<const float4*>(
                    Wg + (size_t)r * D_DIM + kc + c4);
                Ws[c4 + 0][r] = v.x; Ws[c4 + 1][r] = v.y;
                Ws[c4 + 2][r] = v.z; Ws[c4 + 3][r] = v.w;
            }
        }
        __syncthreads();
#pragma unroll 8
        for (int kk = 0; kk < GL_BK; kk++) {
            const float a = As[kk][row];
            float4 w0 = *reinterpret_cast<float4*>(&Ws[kk][ch]);
            float4 w1 = *reinterpret_cast<float4*>(&Ws[kk][ch + 4]);
            float4 w2 = *reinterpret_cast<float4*>(&Ws[kk][ch + 8]);
            acc[0] += a * w0.x; acc[1] += a * w0.y;
            acc[2] += a * w0.z; acc[3] += a * w0.w;
            acc[4] += a * w1.x; acc[5] += a * w1.y;
            acc[6] += a * w1.z; acc[7] += a * w1.w;
            acc[8] += a * w2.x; acc[9] += a * w2.y;
            acc[10] += a * w2.z; acc[11] += a * w2.w;
        }
        __syncthreads();
    }
    float* dst = g_logit + (size_t)(m0 + row) * NEXP + ch;
#pragma unroll
    for (int j = 0; j < 12; j++) dst[j] = acc[j];
}

// ---------------------------------------------------------------------------
// HMMA GEMM with fused expert-sum epilogue (R5 verbatim).
// Grid (24 experts, 128 m-tiles), x fastest -> wave shares A bands across
// experts (24x A L2 reuse). 128 threads = 4 warps (2m x 2n), 64x64 wtile.
// ---------------------------------------------------------------------------
__global__ __launch_bounds__(128, 2) void gemm_hmma()
{
    extern __shared__ char smem[];
    const uint32_t sb = smem_u32(smem);
    const int tid = threadIdx.x;
    const int lane = tid & 31, warp = tid >> 5;
    const int wm = warp & 1, wn = warp >> 1;     // 2m x 2n
    const int nt = blockIdx.x;                    // 0..23 (global expert)
    const int m0 = blockIdx.y * BM;
    const size_t brow0 = (size_t)nt * BN;

    float acc[4][8][4];
#pragma unroll
    for (int mi = 0; mi < 4; mi++)
#pragma unroll
        for (int ni = 0; ni < 8; ni++)
#pragma unroll
            for (int j = 0; j < 4; j++) acc[mi][ni][j] = 0.f;

    auto load_stage = [&](int step) {
        if (step < NSTEPS) {
            const int p = (step >= 2 * KSTEPS) ? 2 : (step >= KSTEPS ? 1 : 0);
            const int k0 = (step - p * KSTEPS) * KB;
            const __nv_bfloat16* Asrc = (p == 1) ? g_Alo : g_Ahi;
            const __nv_bfloat16* Bsrc = (p == 2) ? g_Blo : g_Bhi;
            const uint32_t a_base = sb + (step % STAGES) * STAGE_BYTES;
            const uint32_t b_base = a_base + A_BYTES;
#pragma unroll
            for (int i = 0; i < 8; i++) {
                const int idx = i * 128 + tid;
                const int r = idx >> 3, c = idx & 7;
                cpa16(a_base + swz(r * 128 + c * 16),
                      Asrc + (size_t)(m0 + r) * D_DIM + k0 + c * 8);
            }
#pragma unroll
            for (int i = 0; i < 8; i++) {
                const int idx = i * 128 + tid;
                const int r = idx >> 3, c = idx & 7;
                cpa16(b_base + swz(r * 128 + c * 16),
                      Bsrc + (brow0 + r) * D_DIM + k0 + c * 8);
            }
        }
        cpa_commit();
    };

    load_stage(0); load_stage(1);

    const int arow = wm * 64 + (lane & 15);
    const int brow = wn * 64 + (lane & 15);
    const int khalf = (lane >> 4) * 16;

    for (int step = 0; step < NSTEPS; ++step) {
        cpa_wait1();
        __syncthreads();
        load_stage(step + 2);

        const uint32_t a_base = sb + (step % STAGES) * STAGE_BYTES;
        const uint32_t b_base = a_base + A_BYTES;
#pragma unroll
        for (int k16 = 0; k16 < 4; k16++) {
            const int kb = k16 * 32 + khalf;
            uint32_t a[4][4], bb[4][4];
#pragma unroll
            for (int mi = 0; mi < 4; mi++)
                ldsm_x4(a[mi], a_base + swz((arow + mi * 16) * 128 + kb));
#pragma unroll
            for (int nj = 0; nj < 4; nj++)
                ldsm_x4(bb[nj], b_base + swz((brow + nj * 16) * 128 + kb));
#pragma unroll
            for (int mi = 0; mi < 4; mi++)
#pragma unroll
                for (int ni = 0; ni < 8; ni++)
                    mma16816(acc[mi][ni], a[mi],
                             bb[ni >> 1][ni & 1], bb[ni >> 1][(ni & 1) + 2]);
        }
    }

    // ---- Fused epilogue: pair products -> per-row expert sum ----
    __syncthreads();
    float* esum = reinterpret_cast<float*>(smem);   // [128]
    esum[tid] = 0.f;
    __syncthreads();

#pragma unroll
    for (int mi = 0; mi < 4; mi++) {
        float pl = 0.f, ph = 0.f;
#pragma unroll
        for (int ni = 0; ni < 8; ni++) {
            pl += acc[mi][ni][0] * acc[mi][ni][1];
            ph += acc[mi][ni][2] * acc[mi][ni][3];
        }
        pl += __shfl_xor_sync(0xffffffffu, pl, 1);
        pl += __shfl_xor_sync(0xffffffffu, pl, 2);
        ph += __shfl_xor_sync(0xffffffffu, ph, 1);
        ph += __shfl_xor_sync(0xffffffffu, ph, 2);
        if ((lane & 3) == 0) {
            const int r = wm * 64 + mi * 16 + (lane >> 2);
            atomicAdd(&esum[r], pl);
            atomicAdd(&esum[r + 8], ph);
        }
    }
    __syncthreads();
    g_e0[(size_t)(m0 + tid) * NEXP + nt] = esum[tid];
}

// ---------------------------------------------------------------------------
// compute_c: per-row scalar recurrence (one thread per row).
// ---------------------------------------------------------------------------
__global__ __launch_bounds__(256) void compute_c(const float* __restrict__ bg)
{
    const int b = blockIdx.x * 256 + threadIdx.x;
    const float* e0 = g_e0 + (size_t)b * NEXP;
    const float* lg = g_logit + (size_t)b * NEXP;
    float c = 1.f;
#pragma unroll
    for (int l = 0; l < L_LAYERS; l++) {
        const int base = l * E_EXP;
        float logit[E_EXP], mx = -1e30f;
#pragma unroll
        for (int e = 0; e < E_EXP; e++) {
            logit[e] = c * lg[base + e] + bg[base + e];
            mx = fmaxf(mx, logit[e]);
        }
        float se = 0.f, acc = 0.f;
#pragma unroll
        for (int e = 0; e < E_EXP; e++) {
            const float ge = expf(logit[e] - mx);
            se += ge;
            acc += ge * e0[base + e];
        }
        c += c * c * (acc / se);
    }
    g_c[b] = c;
}

// ---------------------------------------------------------------------------
// scale: out = c[row] * X0. Coalesced grid-stride float4 streaming.
// ---------------------------------------------------------------------------
#define SC_BLOCKS 4096
__global__ __launch_bounds__(256) void scale_out(
    const float* __restrict__ X0, float* __restrict__ out)
{
    const size_t total4 = (size_t)B_ROWS * D_DIM / 4;       // 8388608
    const size_t stride = (size_t)SC_BLOCKS * 256;           // 1048576
    size_t j = (size_t)blockIdx.x * 256 + threadIdx.x;
    const float4* x4 = reinterpret_cast<const float4*>(X0);
    float4* o4 = reinterpret_cast<float4*>(out);
#pragma unroll
    for (int i = 0; i < 8; i++, j += stride) {
        if (j < total4) {
            const float c = g_c[j >> 9];     // 512 float4 per row
            float4 x = x4[j];
            x.x *= c; x.y *= c; x.z *= c; x.w *= c;
            o4[j] = x;
        }
    }
}

// ---------------------------------------------------------------------------
// Launch
// ---------------------------------------------------------------------------
extern "C" void kernel_launch(void* const* d_in, const int* in_sizes, int n_in,
                              void* d_out, int out_size) {
    const float* X0 = (const float*)d_in[0];
    const float* U  = (const float*)d_in[1];
    const float* V  = (const float*)d_in[2];
    const float* Wg = (const float*)d_in[3];
    const float* bg = (const float*)d_in[4];
    float* out = (float*)d_out;

    cudaFuncSetAttribute(gemm_hmma, cudaFuncAttributeMaxDynamicSharedMemorySize,
                         SMEM_TOTAL);

    prep_weights<<<NCOL, 256>>>(U, V);
    split_x0<<<(B_ROWS * D_DIM) / (256 * 16), 256>>>(X0);
    gate_logits<<<B_ROWS / GL_BM, 256>>>(X0, Wg);
    gemm_hmma<<<dim3(NEXP, B_ROWS / BM), 128, SMEM_TOTAL>>>();
    compute_c<<<B_ROWS / 256, 256>>>(bg);
    scale_out<<<SC_BLOCKS, 256>>>(X0, out);
}

// round 12
// speedup vs baseline: 1.0880x; 1.0003x over previous
#include <cuda_runtime.h>
#include <cuda_bf16.h>
#include <cstdint>

// ---------------------------------------------------------------------------
// Problem constants
// ---------------------------------------------------------------------------
#define B_ROWS   16384
#define D_DIM    2048
#define L_LAYERS 3
#define E_EXP    8
#define NCOL     (L_LAYERS * 1024)   // 3072 interleaved U/V columns (all layers)
#define NEXP     (L_LAYERS * E_EXP)  // 24

// GEMM tiling (R5 config): 128x128 tile, 4 warps (2m x 2n), 64x64 warp tile,
// 3 stages, 2 CTAs/SM.
#define BM 128
#define BN 128
#define KB 64                         // bf16 per k-step (128 B rows)
#define STAGES 3
#define KSTEPS (D_DIM / KB)           // 32
#define NSTEPS (3 * KSTEPS)           // 96: phases hh, lh, hl
#define A_BYTES (BM * 128)            // 16 KB
#define B_BYTES (BN * 128)            // 16 KB
#define STAGE_BYTES (A_BYTES + B_BYTES)      // 32 KB
#define SMEM_TOTAL (STAGES * STAGE_BYTES)    // 96 KB -> 2 CTAs/SM

// ---------------------------------------------------------------------------
// Device scratch (static)
// ---------------------------------------------------------------------------
__device__ __nv_bfloat16 g_Ahi[(size_t)B_ROWS * D_DIM];
__device__ __nv_bfloat16 g_Alo[(size_t)B_ROWS * D_DIM];
__device__ __nv_bfloat16 g_Bhi[(size_t)NCOL * D_DIM];
__device__ __nv_bfloat16 g_Blo[(size_t)NCOL * D_DIM];
__device__ float         g_e0[(size_t)B_ROWS * NEXP];
__device__ float         g_logit[(size_t)B_ROWS * NEXP];

// ---------------------------------------------------------------------------
// Helpers
// ---------------------------------------------------------------------------
__device__ __forceinline__ uint32_t smem_u32(const void* p) {
    uint32_t a;
    asm("{ .reg .u64 t; cvta.to.shared.u64 t, %1; cvt.u32.u64 %0, t; }"
        : "=r"(a) : "l"(p));
    return a;
}
__device__ __forceinline__ uint32_t swz(uint32_t off) {        // SW128
    return off ^ ((off >> 3) & 0x70);
}
__device__ __forceinline__ void cpa16(uint32_t dst, const void* src) {
    asm volatile("cp.async.cg.shared.global [%0], [%1], 16;"
                 :: "r"(dst), "l"(src) : "memory");
}
__device__ __forceinline__ void cpa_commit() {
    asm volatile("cp.async.commit_group;" ::: "memory");
}
__device__ __forceinline__ void cpa_wait1() {
    asm volatile("cp.async.wait_group 1;" ::: "memory");
}
__device__ __forceinline__ void ldsm_x4(uint32_t* r, uint32_t addr) {
    asm volatile("ldmatrix.sync.aligned.m8n8.x4.shared.b16 {%0,%1,%2,%3}, [%4];"
                 : "=r"(r[0]), "=r"(r[1]), "=r"(r[2]), "=r"(r[3]) : "r"(addr));
}
__device__ __forceinline__ void mma16816(float* d, const uint32_t* a,
                                         uint32_t b0, uint32_t b1) {
    asm volatile(
        "mma.sync.aligned.m16n8k16.row.col.f32.bf16.bf16.f32 "
        "{%0,%1,%2,%3}, {%4,%5,%6,%7}, {%8,%9}, {%0,%1,%2,%3};"
        : "+f"(d[0]), "+f"(d[1]), "+f"(d[2]), "+f"(d[3])
        : "r"(a[0]), "r"(a[1]), "r"(a[2]), "r"(a[3]), "r"(b0), "r"(b1));
}

// ---------------------------------------------------------------------------
// Merged prep: THREE DISJOINT BLOCK RANGES, each block runs exactly one of
// the R11 per-block bodies (no intra-block fusion — that was the R10 bug).
//   [0, 128)            : gate_logits (compute-bound, scheduled first)
//   [128, 128+NCOL)     : weight split
//   [3200, 3200+8192)   : X0 hi/lo split (streaming)
// ---------------------------------------------------------------------------
#define GL_BM 128
#define GL_BK 64
#define PREP_GATE   128
#define PREP_WB     (PREP_GATE + NCOL)            // 3200
#define PREP_TOTAL  (PREP_WB + 8192)              // 11392

__global__ __launch_bounds__(256) void prep_all(
    const float* __restrict__ U, const float* __restrict__ V,
    const float* __restrict__ X0, const float* __restrict__ Wg)
{
    const int tid = threadIdx.x;

    if (blockIdx.x >= PREP_WB) {
        // ---- X0 split: streaming, 16 floats/thread ----
        const size_t base =
            (((size_t)(blockIdx.x - PREP_WB)) * 256 + tid) * 16;
#pragma unroll
        for (int cidx = 0; cidx < 4; cidx++) {
            const size_t idx = base + cidx * 4;
            float4 v = *reinterpret_cast<const float4*>(X0 + idx);
            float vv[4] = {v.x, v.y, v.z, v.w};
            __nv_bfloat16 hi[4], lo[4];
#pragma unroll
            for (int j = 0; j < 4; j++) {
                hi[j] = __float2bfloat16(vv[j]);
                lo[j] = __float2bfloat16(vv[j] - __bfloat162float(hi[j]));
            }
            *reinterpret_cast<uint2*>(&g_Ahi[idx]) = *reinterpret_cast<uint2*>(hi);
            *reinterpret_cast<uint2*>(&g_Alo[idx]) = *reinterpret_cast<uint2*>(lo);
        }
        return;
    }

    if (blockIdx.x >= PREP_GATE) {
        // ---- weight split: one block per interleaved column ----
        const int row = blockIdx.x - PREP_GATE;
        const int l = row >> 10, c = row & 1023;
        const int e = c >> 7, i = c & 127, r = i >> 1, uv = i & 1;
        const float* src = (uv ? V : U)
                         + (((size_t)(l * E_EXP + e)) * 64 + r) * D_DIM;
        const size_t dst = (size_t)row * D_DIM;
        const int k = tid * 8;
        float4 a = *reinterpret_cast<const float4*>(src + k);
        float4 b = *reinterpret_cast<const float4*>(src + k + 4);
        float v[8] = {a.x, a.y, a.z, a.w, b.x, b.y, b.z, b.w};
        __nv_bfloat16 hi[8], lo[8];
#pragma unroll
        for (int j = 0; j < 8; j++) {
            hi[j] = __float2bfloat16(v[j]);
            lo[j] = __float2bfloat16(v[j] - __bfloat162float(hi[j]));
        }
        *reinterpret_cast<uint4*>(&g_Bhi[dst + k]) = *reinterpret_cast<uint4*>(hi);
        *reinterpret_cast<uint4*>(&g_Blo[dst + k]) = *reinterpret_cast<uint4*>(lo);
        return;
    }

    // ---- gate logits (R11 body, unchanged) ----
    __shared__ float As[GL_BK][GL_BM + 1];
    __shared__ float Ws[GL_BK][36];
    const int m0 = blockIdx.x * GL_BM;
    const int row = tid >> 1;
    const int ch = (tid & 1) * 12;
    float acc[12];
#pragma unroll
    for (int j = 0; j < 12; j++) acc[j] = 0.f;

    for (int kc = 0; kc < D_DIM; kc += GL_BK) {
#pragma unroll
        for (int i = 0; i < 8; i++) {
            const int idx = i * 256 + tid;
            const int r = idx >> 4, c4 = (idx & 15) * 4;
            float4 v = *reinterpret_cast<const float4*>(
                X0 + (size_t)(m0 + r) * D_DIM + kc + c4);
            As[c4 + 0][r] = v.x; As[c4 + 1][r] = v.y;
            As[c4 + 2][r] = v.z; As[c4 + 3][r] = v.w;
        }
#pragma unroll
        for (int i = 0; i < 2; i++) {
            const int idx = i * 256 + tid;
            if (idx < 384) {
                const int r = idx >> 4, c4 = (idx & 15) * 4;
                float4 v = *reinterpret_cast<const float4*>(
                    Wg + (size_t)r * D_DIM + kc + c4);
                Ws[c4 + 0][r] = v.x; Ws[c4 + 1][r] = v.y;
                Ws[c4 + 2][r] = v.z; Ws[c4 + 3][r] = v.w;
            }
        }
        __syncthreads();
#pragma unroll 8
        for (int kk = 0; kk < GL_BK; kk++) {
            const float a = As[kk][row];
            float4 w0 = *reinterpret_cast<float4*>(&Ws[kk][ch]);
            float4 w1 = *reinterpret_cast<float4*>(&Ws[kk][ch + 4]);
            float4 w2 = *reinterpret_cast<float4*>(&Ws[kk][ch + 8]);
            acc[0] += a * w0.x; acc[1] += a * w0.y;
            acc[2] += a * w0.z; acc[3] += a * w0.w;
            acc[4] += a * w1.x; acc[5] += a * w1.y;
            acc[6] += a * w1.z; acc[7] += a * w1.w;
            acc[8] += a * w2.x; acc[9] += a * w2.y;
            acc[10] += a * w2.z; acc[11] += a * w2.w;
        }
        __syncthreads();
    }
    float* dst = g_logit + (size_t)(m0 + row) * NEXP + ch;
#pragma unroll
    for (int j = 0; j < 12; j++) dst[j] = acc[j];
}

// ---------------------------------------------------------------------------
// HMMA GEMM with fused expert-sum epilogue (R5 verbatim).
// Grid (24 experts, 128 m-tiles), x fastest -> wave shares A bands across
// experts (24x A L2 reuse). 128 threads = 4 warps (2m x 2n), 64x64 wtile.
// ---------------------------------------------------------------------------
__global__ __launch_bounds__(128, 2) void gemm_hmma()
{
    extern __shared__ char smem[];
    const uint32_t sb = smem_u32(smem);
    const int tid = threadIdx.x;
    const int lane = tid & 31, warp = tid >> 5;
    const int wm = warp & 1, wn = warp >> 1;     // 2m x 2n
    const int nt = blockIdx.x;                    // 0..23 (global expert)
    const int m0 = blockIdx.y * BM;
    const size_t brow0 = (size_t)nt * BN;

    float acc[4][8][4];
#pragma unroll
    for (int mi = 0; mi < 4; mi++)
#pragma unroll
        for (int ni = 0; ni < 8; ni++)
#pragma unroll
            for (int j = 0; j < 4; j++) acc[mi][ni][j] = 0.f;

    auto load_stage = [&](int step) {
        if (step < NSTEPS) {
            const int p = (step >= 2 * KSTEPS) ? 2 : (step >= KSTEPS ? 1 : 0);
            const int k0 = (step - p * KSTEPS) * KB;
            const __nv_bfloat16* Asrc = (p == 1) ? g_Alo : g_Ahi;
            const __nv_bfloat16* Bsrc = (p == 2) ? g_Blo : g_Bhi;
            const uint32_t a_base = sb + (step % STAGES) * STAGE_BYTES;
            const uint32_t b_base = a_base + A_BYTES;
#pragma unroll
            for (int i = 0; i < 8; i++) {
                const int idx = i * 128 + tid;
                const int r = idx >> 3, c = idx & 7;
                cpa16(a_base + swz(r * 128 + c * 16),
                      Asrc + (size_t)(m0 + r) * D_DIM + k0 + c * 8);
            }
#pragma unroll
            for (int i = 0; i < 8; i++) {
                const int idx = i * 128 + tid;
                const int r = idx >> 3, c = idx & 7;
                cpa16(b_base + swz(r * 128 + c * 16),
                      Bsrc + (brow0 + r) * D_DIM + k0 + c * 8);
            }
        }
        cpa_commit();
    };

    load_stage(0); load_stage(1);

    const int arow = wm * 64 + (lane & 15);
    const int brow = wn * 64 + (lane & 15);
    const int khalf = (lane >> 4) * 16;

    for (int step = 0; step < NSTEPS; ++step) {
        cpa_wait1();
        __syncthreads();
        load_stage(step + 2);

        const uint32_t a_base = sb + (step % STAGES) * STAGE_BYTES;
        const uint32_t b_base = a_base + A_BYTES;
#pragma unroll
        for (int k16 = 0; k16 < 4; k16++) {
            const int kb = k16 * 32 + khalf;
            uint32_t a[4][4], bb[4][4];
#pragma unroll
            for (int mi = 0; mi < 4; mi++)
                ldsm_x4(a[mi], a_base + swz((arow + mi * 16) * 128 + kb));
#pragma unroll
            for (int nj = 0; nj < 4; nj++)
                ldsm_x4(bb[nj], b_base + swz((brow + nj * 16) * 128 + kb));
#pragma unroll
            for (int mi = 0; mi < 4; mi++)
#pragma unroll
                for (int ni = 0; ni < 8; ni++)
                    mma16816(acc[mi][ni], a[mi],
                             bb[ni >> 1][ni & 1], bb[ni >> 1][(ni & 1) + 2]);
        }
    }

    // ---- Fused epilogue: pair products -> per-row expert sum ----
    __syncthreads();
    float* esum = reinterpret_cast<float*>(smem);   // [128]
    esum[tid] = 0.f;
    __syncthreads();

#pragma unroll
    for (int mi = 0; mi < 4; mi++) {
        float pl = 0.f, ph = 0.f;
#pragma unroll
        for (int ni = 0; ni < 8; ni++) {
            pl += acc[mi][ni][0] * acc[mi][ni][1];
            ph += acc[mi][ni][2] * acc[mi][ni][3];
        }
        pl += __shfl_xor_sync(0xffffffffu, pl, 1);
        pl += __shfl_xor_sync(0xffffffffu, pl, 2);
        ph += __shfl_xor_sync(0xffffffffu, ph, 1);
        ph += __shfl_xor_sync(0xffffffffu, ph, 2);
        if ((lane & 3) == 0) {
            const int r = wm * 64 + mi * 16 + (lane >> 2);
            atomicAdd(&esum[r], pl);
            atomicAdd(&esum[r + 8], ph);
        }
    }
    __syncthreads();
    g_e0[(size_t)(m0 + tid) * NEXP + nt] = esum[tid];
}

// ---------------------------------------------------------------------------
// Fused finalize: block = 4 contiguous rows. Threads 0..3 run the scalar
// recurrence; all 256 threads then scale the 4 rows (coalesced float4).
// ---------------------------------------------------------------------------
__global__ __launch_bounds__(256) void finalize(
    const float* __restrict__ X0, const float* __restrict__ bg,
    float* __restrict__ out)
{
    __shared__ float sc[4];
    const int t = threadIdx.x;
    const int b0 = blockIdx.x * 4;

    if (t < 4) {
        const int b = b0 + t;
        const float* e0 = g_e0 + (size_t)b * NEXP;
        const float* lg = g_logit + (size_t)b * NEXP;
        float c = 1.f;
#pragma unroll
        for (int l = 0; l < L_LAYERS; l++) {
            const int base = l * E_EXP;
            float logit[E_EXP], mx = -1e30f;
#pragma unroll
            for (int e = 0; e < E_EXP; e++) {
                logit[e] = c * lg[base + e] + bg[base + e];
                mx = fmaxf(mx, logit[e]);
            }
            float se = 0.f, acc = 0.f;
#pragma unroll
            for (int e = 0; e < E_EXP; e++) {
                const float ge = expf(logit[e] - mx);
                se += ge;
                acc += ge * e0[base + e];
            }
            c += c * c * (acc / se);
        }
        sc[t] = c;
    }
    __syncthreads();

    // 4 rows = 2048 float4, 256 threads x 8 iters, coalesced
    const size_t base4 = (size_t)b0 * (D_DIM / 4);
    const float4* x4 = reinterpret_cast<const float4*>(X0) + base4;
    float4* o4 = reinterpret_cast<float4*>(out) + base4;
#pragma unroll
    for (int i = 0; i < 8; i++) {
        const int j = i * 256 + t;
        const float c = sc[j >> 9];          // 512 float4 per row
        float4 x = x4[j];
        x.x *= c; x.y *= c; x.z *= c; x.w *= c;
        o4[j] = x;
    }
}

// ---------------------------------------------------------------------------
// Launch: 3 kernels total.
// ---------------------------------------------------------------------------
extern "C" void kernel_launch(void* const* d_in, const int* in_sizes, int n_in,
                              void* d_out, int out_size) {
    const float* X0 = (const float*)d_in[0];
    const float* U  = (const float*)d_in[1];
    const float* V  = (const float*)d_in[2];
    const float* Wg = (const float*)d_in[3];
    const float* bg = (const float*)d_in[4];
    float* out = (float*)d_out;

    cudaFuncSetAttribute(gemm_hmma, cudaFuncAttributeMaxDynamicSharedMemorySize,
                         SMEM_TOTAL);

    prep_all<<<PREP_TOTAL, 256>>>(U, V, X0, Wg);
    gemm_hmma<<<dim3(NEXP, B_ROWS / BM), 128, SMEM_TOTAL>>>();
    finalize<<<B_ROWS / 4, 256>>>(X0, bg, out);
}

// round 13
// speedup vs baseline: 1.0931x; 1.0046x over previous
#include <cuda_runtime.h>
#include <cuda_bf16.h>
#include <cstdint>

// ---------------------------------------------------------------------------
// Problem constants
// ---------------------------------------------------------------------------
#define B_ROWS   16384
#define D_DIM    2048
#define L_LAYERS 3
#define E_EXP    8
#define NCOL     (L_LAYERS * 1024)   // 3072 interleaved U/V columns (all layers)
#define NEXP     (L_LAYERS * E_EXP)  // 24

// GEMM tiling (R5 config): 128x128 tile, 4 warps (2m x 2n), 64x64 warp tile,
// 3 stages, 2 CTAs/SM.
#define BM 128
#define BN 128
#define KB 64                         // bf16 per k-step (128 B rows)
#define STAGES 3
#define KSTEPS (D_DIM / KB)           // 32
#define NSTEPS (3 * KSTEPS)           // 96: phases hh, lh, hl
#define A_BYTES (BM * 128)            // 16 KB
#define B_BYTES (BN * 128)            // 16 KB
#define STAGE_BYTES (A_BYTES + B_BYTES)      // 32 KB
#define SMEM_TOTAL (STAGES * STAGE_BYTES)    // 96 KB -> 2 CTAs/SM

// ---------------------------------------------------------------------------
// Device scratch (static)
// ---------------------------------------------------------------------------
__device__ __nv_bfloat16 g_Ahi[(size_t)B_ROWS * D_DIM];
__device__ __nv_bfloat16 g_Alo[(size_t)B_ROWS * D_DIM];
__device__ __nv_bfloat16 g_Bhi[(size_t)NCOL * D_DIM];
__device__ __nv_bfloat16 g_Blo[(size_t)NCOL * D_DIM];
__device__ float         g_e0[(size_t)B_ROWS * NEXP];
__device__ float         g_logit[(size_t)B_ROWS * NEXP];

// ---------------------------------------------------------------------------
// Helpers
// ---------------------------------------------------------------------------
__device__ __forceinline__ uint32_t smem_u32(const void* p) {
    uint32_t a;
    asm("{ .reg .u64 t; cvta.to.shared.u64 t, %1; cvt.u32.u64 %0, t; }"
        : "=r"(a) : "l"(p));
    return a;
}
__device__ __forceinline__ uint32_t swz(uint32_t off) {        // SW128
    return off ^ ((off >> 3) & 0x70);
}
__device__ __forceinline__ void cpa16(uint32_t dst, const void* src) {
    asm volatile("cp.async.cg.shared.global [%0], [%1], 16;"
                 :: "r"(dst), "l"(src) : "memory");
}
__device__ __forceinline__ void cpa_commit() {
    asm volatile("cp.async.commit_group;" ::: "memory");
}
__device__ __forceinline__ void cpa_wait1() {
    asm volatile("cp.async.wait_group 1;" ::: "memory");
}
__device__ __forceinline__ void ldsm_x4(uint32_t* r, uint32_t addr) {
    asm volatile("ldmatrix.sync.aligned.m8n8.x4.shared.b16 {%0,%1,%2,%3}, [%4];"
                 : "=r"(r[0]), "=r"(r[1]), "=r"(r[2]), "=r"(r[3]) : "r"(addr));
}
__device__ __forceinline__ void mma16816(float* d, const uint32_t* a,
                                         uint32_t b0, uint32_t b1) {
    asm volatile(
        "mma.sync.aligned.m16n8k16.row.col.f32.bf16.bf16.f32 "
        "{%0,%1,%2,%3}, {%4,%5,%6,%7}, {%8,%9}, {%0,%1,%2,%3};"
        : "+f"(d[0]), "+f"(d[1]), "+f"(d[2]), "+f"(d[3])
        : "r"(a[0]), "r"(a[1]), "r"(a[2]), "r"(a[3]), "r"(b0), "r"(b1));
}

// split 8 consecutive floats -> uint4 of hi bf16 + uint4 of lo bf16
__device__ __forceinline__ void split8(const float* src,
                                       __nv_bfloat16* dhi, __nv_bfloat16* dlo)
{
    float4 a = *reinterpret_cast<const float4*>(src);
    float4 b = *reinterpret_cast<const float4*>(src + 4);
    float v[8] = {a.x, a.y, a.z, a.w, b.x, b.y, b.z, b.w};
    __nv_bfloat16 hi[8], lo[8];
#pragma unroll
    for (int j = 0; j < 8; j++) {
        hi[j] = __float2bfloat16(v[j]);
        lo[j] = __float2bfloat16(v[j] - __bfloat162float(hi[j]));
    }
    *reinterpret_cast<uint4*>(dhi) = *reinterpret_cast<uint4*>(hi);
    *reinterpret_cast<uint4*>(dlo) = *reinterpret_cast<uint4*>(lo);
}

// ---------------------------------------------------------------------------
// Merged prep: three disjoint block ranges.
//   [0, 128)          : gate logits (fp32 compute, 21 KB smem)
//   [128, 3200)       : weight split (streaming)
//   [3200, 11392)     : X0 hi/lo split (streaming, uint4 stores)
// ---------------------------------------------------------------------------
#define GL_BM 128
#define GL_BK 32
#define PREP_GATE   128
#define PREP_WB     (PREP_GATE + NCOL)            // 3200
#define PREP_TOTAL  (PREP_WB + 8192)              // 11392

__global__ __launch_bounds__(256) void prep_all(
    const float* __restrict__ U, const float* __restrict__ V,
    const float* __restrict__ X0, const float* __restrict__ Wg)
{
    const int tid = threadIdx.x;

    if (blockIdx.x >= PREP_WB) {
        // ---- X0 split: streaming, 16 floats/thread, uint4 stores ----
        const size_t base =
            (((size_t)(blockIdx.x - PREP_WB)) * 256 + tid) * 16;
#pragma unroll
        for (int g = 0; g < 2; g++) {
            const size_t idx = base + g * 8;
            split8(X0 + idx, &g_Ahi[idx], &g_Alo[idx]);
        }
        return;
    }

    if (blockIdx.x >= PREP_GATE) {
        // ---- weight split: one block per interleaved column ----
        const int row = blockIdx.x - PREP_GATE;
        const int l = row >> 10, c = row & 1023;
        const int e = c >> 7, i = c & 127, r = i >> 1, uv = i & 1;
        const float* src = (uv ? V : U)
                         + (((size_t)(l * E_EXP + e)) * 64 + r) * D_DIM;
        const size_t dst = (size_t)row * D_DIM + tid * 8;
        split8(src + tid * 8, &g_Bhi[dst], &g_Blo[dst]);
        return;
    }

    // ---- gate logits (GL_BK = 32 -> 21 KB smem) ----
    __shared__ float As[GL_BK][GL_BM + 1];
    __shared__ float Ws[GL_BK][36];
    const int m0 = blockIdx.x * GL_BM;
    const int row = tid >> 1;
    const int ch = (tid & 1) * 12;
    float acc[12];
#pragma unroll
    for (int j = 0; j < 12; j++) acc[j] = 0.f;

    for (int kc = 0; kc < D_DIM; kc += GL_BK) {
        // stage X0 tile: 128 rows x 32 k = 1024 float4, 4 per thread
#pragma unroll
        for (int i = 0; i < 4; i++) {
            const int idx = i * 256 + tid;
            const int r = idx >> 3, c4 = (idx & 7) * 4;
            float4 v = *reinterpret_cast<const float4*>(
                X0 + (size_t)(m0 + r) * D_DIM + kc + c4);
            As[c4 + 0][r] = v.x; As[c4 + 1][r] = v.y;
            As[c4 + 2][r] = v.z; As[c4 + 3][r] = v.w;
        }
        // stage Wg tile: 24 rows x 32 k = 192 float4
        if (tid < 192) {
            const int r = tid >> 3, c4 = (tid & 7) * 4;
            float4 v = *reinterpret_cast<const float4*>(
                Wg + (size_t)r * D_DIM + kc + c4);
            Ws[c4 + 0][r] = v.x; Ws[c4 + 1][r] = v.y;
            Ws[c4 + 2][r] = v.z; Ws[c4 + 3][r] = v.w;
        }
        __syncthreads();
#pragma unroll 8
        for (int kk = 0; kk < GL_BK; kk++) {
            const float a = As[kk][row];
            float4 w0 = *reinterpret_cast<float4*>(&Ws[kk][ch]);
            float4 w1 = *reinterpret_cast<float4*>(&Ws[kk][ch + 4]);
            float4 w2 = *reinterpret_cast<float4*>(&Ws[kk][ch + 8]);
            acc[0] += a * w0.x; acc[1] += a * w0.y;
            acc[2] += a * w0.z; acc[3] += a * w0.w;
            acc[4] += a * w1.x; acc[5] += a * w1.y;
            acc[6] += a * w1.z; acc[7] += a * w1.w;
            acc[8] += a * w2.x; acc[9] += a * w2.y;
            acc[10] += a * w2.z; acc[11] += a * w2.w;
        }
        __syncthreads();
    }
    float* dst = g_logit + (size_t)(m0 + row) * NEXP + ch;
#pragma unroll
    for (int j = 0; j < 12; j++) dst[j] = acc[j];
}

// ---------------------------------------------------------------------------
// HMMA GEMM with fused expert-sum epilogue (R5 verbatim — established optimum).
// ---------------------------------------------------------------------------
__global__ __launch_bounds__(128, 2) void gemm_hmma()
{
    extern __shared__ char smem[];
    const uint32_t sb = smem_u32(smem);
    const int tid = threadIdx.x;
    const int lane = tid & 31, warp = tid >> 5;
    const int wm = warp & 1, wn = warp >> 1;     // 2m x 2n
    const int nt = blockIdx.x;                    // 0..23 (global expert)
    const int m0 = blockIdx.y * BM;
    const size_t brow0 = (size_t)nt * BN;

    float acc[4][8][4];
#pragma unroll
    for (int mi = 0; mi < 4; mi++)
#pragma unroll
        for (int ni = 0; ni < 8; ni++)
#pragma unroll
            for (int j = 0; j < 4; j++) acc[mi][ni][j] = 0.f;

    auto load_stage = [&](int step) {
        if (step < NSTEPS) {
            const int p = (step >= 2 * KSTEPS) ? 2 : (step >= KSTEPS ? 1 : 0);
            const int k0 = (step - p * KSTEPS) * KB;
            const __nv_bfloat16* Asrc = (p == 1) ? g_Alo : g_Ahi;
            const __nv_bfloat16* Bsrc = (p == 2) ? g_Blo : g_Bhi;
            const uint32_t a_base = sb + (step % STAGES) * STAGE_BYTES;
            const uint32_t b_base = a_base + A_BYTES;
#pragma unroll
            for (int i = 0; i < 8; i++) {
                const int idx = i * 128 + tid;
                const int r = idx >> 3, c = idx & 7;
                cpa16(a_base + swz(r * 128 + c * 16),
                      Asrc + (size_t)(m0 + r) * D_DIM + k0 + c * 8);
            }
#pragma unroll
            for (int i = 0; i < 8; i++) {
                const int idx = i * 128 + tid;
                const int r = idx >> 3, c = idx & 7;
                cpa16(b_base + swz(r * 128 + c * 16),
                      Bsrc + (brow0 + r) * D_DIM + k0 + c * 8);
            }
        }
        cpa_commit();
    };

    load_stage(0); load_stage(1);

    const int arow = wm * 64 + (lane & 15);
    const int brow = wn * 64 + (lane & 15);
    const int khalf = (lane >> 4) * 16;

    for (int step = 0; step < NSTEPS; ++step) {
        cpa_wait1();
        __syncthreads();
        load_stage(step + 2);

        const uint32_t a_base = sb + (step % STAGES) * STAGE_BYTES;
        const uint32_t b_base = a_base + A_BYTES;
#pragma unroll
        for (int k16 = 0; k16 < 4; k16++) {
            const int kb = k16 * 32 + khalf;
            uint32_t a[4][4], bb[4][4];
#pragma unroll
            for (int mi = 0; mi < 4; mi++)
                ldsm_x4(a[mi], a_base + swz((arow + mi * 16) * 128 + kb));
#pragma unroll
            for (int nj = 0; nj < 4; nj++)
                ldsm_x4(bb[nj], b_base + swz((brow + nj * 16) * 128 + kb));
#pragma unroll
            for (int mi = 0; mi < 4; mi++)
#pragma unroll
                for (int ni = 0; ni < 8; ni++)
                    mma16816(acc[mi][ni], a[mi],
                             bb[ni >> 1][ni & 1], bb[ni >> 1][(ni & 1) + 2]);
        }
    }

    // ---- Fused epilogue: pair products -> per-row expert sum ----
    __syncthreads();
    float* esum = reinterpret_cast<float*>(smem);   // [128]
    esum[tid] = 0.f;
    __syncthreads();

#pragma unroll
    for (int mi = 0; mi < 4; mi++) {
        float pl = 0.f, ph = 0.f;
#pragma unroll
        for (int ni = 0; ni < 8; ni++) {
            pl += acc[mi][ni][0] * acc[mi][ni][1];
            ph += acc[mi][ni][2] * acc[mi][ni][3];
        }
        pl += __shfl_xor_sync(0xffffffffu, pl, 1);
        pl += __shfl_xor_sync(0xffffffffu, pl, 2);
        ph += __shfl_xor_sync(0xffffffffu, ph, 1);
        ph += __shfl_xor_sync(0xffffffffu, ph, 2);
        if ((lane & 3) == 0) {
            const int r = wm * 64 + mi * 16 + (lane >> 2);
            atomicAdd(&esum[r], pl);
            atomicAdd(&esum[r + 8], ph);
        }
    }
    __syncthreads();
    g_e0[(size_t)(m0 + tid) * NEXP + nt] = esum[tid];
}

// ---------------------------------------------------------------------------
// Fused finalize: block = 4 contiguous rows. Threads 0..3 run the scalar
// recurrence; all 256 threads then scale the 4 rows (coalesced float4).
// ---------------------------------------------------------------------------
__global__ __launch_bounds__(256) void finalize(
    const float* __restrict__ X0, const float* __restrict__ bg,
    float* __restrict__ out)
{
    __shared__ float sc[4];
    const int t = threadIdx.x;
    const int b0 = blockIdx.x * 4;

    if (t < 4) {
        const int b = b0 + t;
        const float* e0 = g_e0 + (size_t)b * NEXP;
        const float* lg = g_logit + (size_t)b * NEXP;
        float c = 1.f;
#pragma unroll
        for (int l = 0; l < L_LAYERS; l++) {
            const int base = l * E_EXP;
            float logit[E_EXP], mx = -1e30f;
#pragma unroll
            for (int e = 0; e < E_EXP; e++) {
                logit[e] = c * lg[base + e] + bg[base + e];
                mx = fmaxf(mx, logit[e]);
            }
            float se = 0.f, acc = 0.f;
#pragma unroll
            for (int e = 0; e < E_EXP; e++) {
                const float ge = expf(logit[e] - mx);
                se += ge;
                acc += ge * e0[base + e];
            }
            c += c * c * (acc / se);
        }
        sc[t] = c;
    }
    __syncthreads();

    const size_t base4 = (size_t)b0 * (D_DIM / 4);
    const float4* x4 = reinterpret_cast<const float4*>(X0) + base4;
    float4* o4 = reinterpret_cast<float4*>(out) + base4;
#pragma unroll
    for (int i = 0; i < 8; i++) {
        const int j = i * 256 + t;
        const float c = sc[j >> 9];          // 512 float4 per row
        float4 x = x4[j];
        x.x *= c; x.y *= c; x.z *= c; x.w *= c;
        o4[j] = x;
    }
}

// ---------------------------------------------------------------------------
// Launch: 3 kernels total.
// ---------------------------------------------------------------------------
extern "C" void kernel_launch(void* const* d_in, const int* in_sizes, int n_in,
                              void* d_out, int out_size) {
    const float* X0 = (const float*)d_in[0];
    const float* U  = (const float*)d_in[1];
    const float* V  = (const float*)d_in[2];
    const float* Wg = (const float*)d_in[3];
    const float* bg = (const float*)d_in[4];
    float* out = (float*)d_out;

    cudaFuncSetAttribute(gemm_hmma, cudaFuncAttributeMaxDynamicSharedMemorySize,
                         SMEM_TOTAL);

    prep_all<<<PREP_TOTAL, 256>>>(U, V, X0, Wg);
    gemm_hmma<<<dim3(NEXP, B_ROWS / BM), 128, SMEM_TOTAL>>>();
    finalize<<<B_ROWS / 4, 256>>>(X0, bg, out);
}

// round 14
// speedup vs baseline: 1.1478x; 1.0500x over previous
#include <cuda_runtime.h>
#include <cuda_bf16.h>
#include <cstdint>

// ---------------------------------------------------------------------------
// Problem constants
// ---------------------------------------------------------------------------
#define B_ROWS   16384
#define D_DIM    2048
#define L_LAYERS 3
#define E_EXP    8
#define NCOL     (L_LAYERS * 1024)   // 3072 interleaved U/V columns (all layers)
#define NEXP     (L_LAYERS * E_EXP)  // 24

// GEMM tiling (R5 config): 128x128 tile, 4 warps (2m x 2n), 64x64 warp tile,
// 3 stages, 2 CTAs/SM.
#define BM 128
#define BN 128
#define KB 64                         // bf16 per k-step (128 B rows)
#define STAGES 3
#define KSTEPS (D_DIM / KB)           // 32
#define NSTEPS (3 * KSTEPS)           // 96: phases hh, lh, hl
#define A_BYTES (BM * 128)            // 16 KB
#define B_BYTES (BN * 128)            // 16 KB
#define STAGE_BYTES (A_BYTES + B_BYTES)      // 32 KB
#define SMEM_TOTAL (STAGES * STAGE_BYTES)    // 96 KB -> 2 CTAs/SM

// Gate K-split
#define GK_SPLIT 4
#define GK_LEN   (D_DIM / GK_SPLIT)   // 512

// ---------------------------------------------------------------------------
// Device scratch (static)
// ---------------------------------------------------------------------------
__device__ __nv_bfloat16 g_Ahi[(size_t)B_ROWS * D_DIM];
__device__ __nv_bfloat16 g_Alo[(size_t)B_ROWS * D_DIM];
__device__ __nv_bfloat16 g_Bhi[(size_t)NCOL * D_DIM];
__device__ __nv_bfloat16 g_Blo[(size_t)NCOL * D_DIM];
__device__ float         g_e0[(size_t)B_ROWS * NEXP];
__device__ float         g_logit_part[(size_t)GK_SPLIT * B_ROWS * NEXP];

// ---------------------------------------------------------------------------
// Helpers
// ---------------------------------------------------------------------------
__device__ __forceinline__ uint32_t smem_u32(const void* p) {
    uint32_t a;
    asm("{ .reg .u64 t; cvta.to.shared.u64 t, %1; cvt.u32.u64 %0, t; }"
        : "=r"(a) : "l"(p));
    return a;
}
__device__ __forceinline__ uint32_t swz(uint32_t off) {        // SW128
    return off ^ ((off >> 3) & 0x70);
}
__device__ __forceinline__ void cpa16(uint32_t dst, const void* src) {
    asm volatile("cp.async.cg.shared.global [%0], [%1], 16;"
                 :: "r"(dst), "l"(src) : "memory");
}
__device__ __forceinline__ void cpa_commit() {
    asm volatile("cp.async.commit_group;" ::: "memory");
}
__device__ __forceinline__ void cpa_wait1() {
    asm volatile("cp.async.wait_group 1;" ::: "memory");
}
__device__ __forceinline__ void ldsm_x4(uint32_t* r, uint32_t addr) {
    asm volatile("ldmatrix.sync.aligned.m8n8.x4.shared.b16 {%0,%1,%2,%3}, [%4];"
                 : "=r"(r[0]), "=r"(r[1]), "=r"(r[2]), "=r"(r[3]) : "r"(addr));
}
__device__ __forceinline__ void mma16816(float* d, const uint32_t* a,
                                         uint32_t b0, uint32_t b1) {
    asm volatile(
        "mma.sync.aligned.m16n8k16.row.col.f32.bf16.bf16.f32 "
        "{%0,%1,%2,%3}, {%4,%5,%6,%7}, {%8,%9}, {%0,%1,%2,%3};"
        : "+f"(d[0]), "+f"(d[1]), "+f"(d[2]), "+f"(d[3])
        : "r"(a[0]), "r"(a[1]), "r"(a[2]), "r"(a[3]), "r"(b0), "r"(b1));
}

// split 8 consecutive floats -> uint4 of hi bf16 + uint4 of lo bf16
__device__ __forceinline__ void split8(const float* src,
                                       __nv_bfloat16* dhi, __nv_bfloat16* dlo)
{
    float4 a = *reinterpret_cast<const float4*>(src);
    float4 b = *reinterpret_cast<const float4*>(src + 4);
    float v[8] = {a.x, a.y, a.z, a.w, b.x, b.y, b.z, b.w};
    __nv_bfloat16 hi[8], lo[8];
#pragma unroll
    for (int j = 0; j < 8; j++) {
        hi[j] = __float2bfloat16(v[j]);
        lo[j] = __float2bfloat16(v[j] - __bfloat162float(hi[j]));
    }
    *reinterpret_cast<uint4*>(dhi) = *reinterpret_cast<uint4*>(hi);
    *reinterpret_cast<uint4*>(dlo) = *reinterpret_cast<uint4*>(lo);
}

// ---------------------------------------------------------------------------
// Merged prep: three disjoint block ranges.
//   [0, 512)          : gate logit partials (128 m-blocks x 4 K-chunks)
//   [512, 3584)       : weight split (streaming)
//   [3584, 11776)     : X0 hi/lo split (streaming, uint4 stores)
// ---------------------------------------------------------------------------
#define GL_BM 128
#define GL_BK 32
#define PREP_GATE   (128 * GK_SPLIT)              // 512
#define PREP_WB     (PREP_GATE + NCOL)            // 3584
#define PREP_TOTAL  (PREP_WB + 8192)              // 11776

__global__ __launch_bounds__(256) void prep_all(
    const float* __restrict__ U, const float* __restrict__ V,
    const float* __restrict__ X0, const float* __restrict__ Wg)
{
    const int tid = threadIdx.x;

    if (blockIdx.x >= PREP_WB) {
        // ---- X0 split: streaming, 16 floats/thread, uint4 stores ----
        const size_t base =
            (((size_t)(blockIdx.x - PREP_WB)) * 256 + tid) * 16;
#pragma unroll
        for (int g = 0; g < 2; g++) {
            const size_t idx = base + g * 8;
            split8(X0 + idx, &g_Ahi[idx], &g_Alo[idx]);
        }
        return;
    }

    if (blockIdx.x >= PREP_GATE) {
        // ---- weight split: one block per interleaved column ----
        const int row = blockIdx.x - PREP_GATE;
        const int l = row >> 10, c = row & 1023;
        const int e = c >> 7, i = c & 127, r = i >> 1, uv = i & 1;
        const float* src = (uv ? V : U)
                         + (((size_t)(l * E_EXP + e)) * 64 + r) * D_DIM;
        const size_t dst = (size_t)row * D_DIM + tid * 8;
        split8(src + tid * 8, &g_Bhi[dst], &g_Blo[dst]);
        return;
    }

    // ---- gate logit partials: block = (m-block, K-chunk) ----
    __shared__ float As[GL_BK][GL_BM + 1];
    __shared__ float Ws[GL_BK][36];
    const int mblk = blockIdx.x >> 2;             // 0..127
    const int kchunk = blockIdx.x & 3;            // 0..3
    const int m0 = mblk * GL_BM;
    const int kbeg = kchunk * GK_LEN;
    const int row = tid >> 1;
    const int ch = (tid & 1) * 12;
    float acc[12];
#pragma unroll
    for (int j = 0; j < 12; j++) acc[j] = 0.f;

    for (int kc = kbeg; kc < kbeg + GK_LEN; kc += GL_BK) {
        // stage X0 tile: 128 rows x 32 k = 1024 float4, 4 per thread
#pragma unroll
        for (int i = 0; i < 4; i++) {
            const int idx = i * 256 + tid;
            const int r = idx >> 3, c4 = (idx & 7) * 4;
            float4 v = *reinterpret_cast<const float4*>(
                X0 + (size_t)(m0 + r) * D_DIM + kc + c4);
            As[c4 + 0][r] = v.x; As[c4 + 1][r] = v.y;
            As[c4 + 2][r] = v.z; As[c4 + 3][r] = v.w;
        }
        // stage Wg tile: 24 rows x 32 k = 192 float4
        if (tid < 192) {
            const int r = tid >> 3, c4 = (tid & 7) * 4;
            float4 v = *reinterpret_cast<const float4*>(
                Wg + (size_t)r * D_DIM + kc + c4);
            Ws[c4 + 0][r] = v.x; Ws[c4 + 1][r] = v.y;
            Ws[c4 + 2][r] = v.z; Ws[c4 + 3][r] = v.w;
        }
        __syncthreads();
#pragma unroll 8
        for (int kk = 0; kk < GL_BK; kk++) {
            const float a = As[kk][row];
            float4 w0 = *reinterpret_cast<float4*>(&Ws[kk][ch]);
            float4 w1 = *reinterpret_cast<float4*>(&Ws[kk][ch + 4]);
            float4 w2 = *reinterpret_cast<float4*>(&Ws[kk][ch + 8]);
            acc[0] += a * w0.x; acc[1] += a * w0.y;
            acc[2] += a * w0.z; acc[3] += a * w0.w;
            acc[4] += a * w1.x; acc[5] += a * w1.y;
            acc[6] += a * w1.z; acc[7] += a * w1.w;
            acc[8] += a * w2.x; acc[9] += a * w2.y;
            acc[10] += a * w2.z; acc[11] += a * w2.w;
        }
        __syncthreads();
    }
    float* dst = g_logit_part + ((size_t)kchunk * B_ROWS + m0 + row) * NEXP + ch;
#pragma unroll
    for (int j = 0; j < 12; j++) dst[j] = acc[j];
}

// ---------------------------------------------------------------------------
// HMMA GEMM with fused expert-sum epilogue (R5 verbatim — established optimum).
// ---------------------------------------------------------------------------
__global__ __launch_bounds__(128, 2) void gemm_hmma()
{
    extern __shared__ char smem[];
    const uint32_t sb = smem_u32(smem);
    const int tid = threadIdx.x;
    const int lane = tid & 31, warp = tid >> 5;
    const int wm = warp & 1, wn = warp >> 1;     // 2m x 2n
    const int nt = blockIdx.x;                    // 0..23 (global expert)
    const int m0 = blockIdx.y * BM;
    const size_t brow0 = (size_t)nt * BN;

    float acc[4][8][4];
#pragma unroll
    for (int mi = 0; mi < 4; mi++)
#pragma unroll
        for (int ni = 0; ni < 8; ni++)
#pragma unroll
            for (int j = 0; j < 4; j++) acc[mi][ni][j] = 0.f;

    auto load_stage = [&](int step) {
        if (step < NSTEPS) {
            const int p = (step >= 2 * KSTEPS) ? 2 : (step >= KSTEPS ? 1 : 0);
            const int k0 = (step - p * KSTEPS) * KB;
            const __nv_bfloat16* Asrc = (p == 1) ? g_Alo : g_Ahi;
            const __nv_bfloat16* Bsrc = (p == 2) ? g_Blo : g_Bhi;
            const uint32_t a_base = sb + (step % STAGES) * STAGE_BYTES;
            const uint32_t b_base = a_base + A_BYTES;
#pragma unroll
            for (int i = 0; i < 8; i++) {
                const int idx = i * 128 + tid;
                const int r = idx >> 3, c = idx & 7;
                cpa16(a_base + swz(r * 128 + c * 16),
                      Asrc + (size_t)(m0 + r) * D_DIM + k0 + c * 8);
            }
#pragma unroll
            for (int i = 0; i < 8; i++) {
                const int idx = i * 128 + tid;
                const int r = idx >> 3, c = idx & 7;
                cpa16(b_base + swz(r * 128 + c * 16),
                      Bsrc + (brow0 + r) * D_DIM + k0 + c * 8);
            }
        }
        cpa_commit();
    };

    load_stage(0); load_stage(1);

    const int arow = wm * 64 + (lane & 15);
    const int brow = wn * 64 + (lane & 15);
    const int khalf = (lane >> 4) * 16;

    for (int step = 0; step < NSTEPS; ++step) {
        cpa_wait1();
        __syncthreads();
        load_stage(step + 2);

        const uint32_t a_base = sb + (step % STAGES) * STAGE_BYTES;
        const uint32_t b_base = a_base + A_BYTES;
#pragma unroll
        for (int k16 = 0; k16 < 4; k16++) {
            const int kb = k16 * 32 + khalf;
            uint32_t a[4][4], bb[4][4];
#pragma unroll
            for (int mi = 0; mi < 4; mi++)
                ldsm_x4(a[mi], a_base + swz((arow + mi * 16) * 128 + kb));
#pragma unroll
            for (int nj = 0; nj < 4; nj++)
                ldsm_x4(bb[nj], b_base + swz((brow + nj * 16) * 128 + kb));
#pragma unroll
            for (int mi = 0; mi < 4; mi++)
#pragma unroll
                for (int ni = 0; ni < 8; ni++)
                    mma16816(acc[mi][ni], a[mi],
                             bb[ni >> 1][ni & 1], bb[ni >> 1][(ni & 1) + 2]);
        }
    }

    // ---- Fused epilogue: pair products -> per-row expert sum ----
    __syncthreads();
    float* esum = reinterpret_cast<float*>(smem);   // [128]
    esum[tid] = 0.f;
    __syncthreads();

#pragma unroll
    for (int mi = 0; mi < 4; mi++) {
        float pl = 0.f, ph = 0.f;
#pragma unroll
        for (int ni = 0; ni < 8; ni++) {
            pl += acc[mi][ni][0] * acc[mi][ni][1];
            ph += acc[mi][ni][2] * acc[mi][ni][3];
        }
        pl += __shfl_xor_sync(0xffffffffu, pl, 1);
        pl += __shfl_xor_sync(0xffffffffu, pl, 2);
        ph += __shfl_xor_sync(0xffffffffu, ph, 1);
        ph += __shfl_xor_sync(0xffffffffu, ph, 2);
        if ((lane & 3) == 0) {
            const int r = wm * 64 + mi * 16 + (lane >> 2);
            atomicAdd(&esum[r], pl);
            atomicAdd(&esum[r + 8], ph);
        }
    }
    __syncthreads();
    g_e0[(size_t)(m0 + tid) * NEXP + nt] = esum[tid];
}

// ---------------------------------------------------------------------------
// Fused finalize: block = 4 contiguous rows. Threads 0..3 run the scalar
// recurrence (summing the 4 gate K-partials); all 256 threads then scale.
// ---------------------------------------------------------------------------
__global__ __launch_bounds__(256) void finalize(
    const float* __restrict__ X0, const float* __restrict__ bg,
    float* __restrict__ out)
{
    __shared__ float sc[4];
    const int t = threadIdx.x;
    const int b0 = blockIdx.x * 4;

    if (t < 4) {
        const int b = b0 + t;
        const float* e0 = g_e0 + (size_t)b * NEXP;
        float lg[NEXP];
#pragma unroll
        for (int e = 0; e < NEXP; e++) {
            float s = 0.f;
#pragma unroll
            for (int p = 0; p < GK_SPLIT; p++)
                s += g_logit_part[((size_t)p * B_ROWS + b) * NEXP + e];
            lg[e] = s;
        }
        float c = 1.f;
#pragma unroll
        for (int l = 0; l < L_LAYERS; l++) {
            const int base = l * E_EXP;
            float logit[E_EXP], mx = -1e30f;
#pragma unroll
            for (int e = 0; e < E_EXP; e++) {
                logit[e] = c * lg[base + e] + bg[base + e];
                mx = fmaxf(mx, logit[e]);
            }
            float se = 0.f, acc = 0.f;
#pragma unroll
            for (int e = 0; e < E_EXP; e++) {
                const float ge = expf(logit[e] - mx);
                se += ge;
                acc += ge * e0[base + e];
            }
            c += c * c * (acc / se);
        }
        sc[t] = c;
    }
    __syncthreads();

    const size_t base4 = (size_t)b0 * (D_DIM / 4);
    const float4* x4 = reinterpret_cast<const float4*>(X0) + base4;
    float4* o4 = reinterpret_cast<float4*>(out) + base4;
#pragma unroll
    for (int i = 0; i < 8; i++) {
        const int j = i * 256 + t;
        const float c = sc[j >> 9];          // 512 float4 per row
        float4 x = x4[j];
        x.x *= c; x.y *= c; x.z *= c; x.w *= c;
        o4[j] = x;
    }
}

// ---------------------------------------------------------------------------
// Launch: 3 kernels total.
// ---------------------------------------------------------------------------
extern "C" void kernel_launch(void* const* d_in, const int* in_sizes, int n_in,
                              void* d_out, int out_size) {
    const float* X0 = (const float*)d_in[0];
    const float* U  = (const float*)d_in[1];
    const float* V  = (const float*)d_in[2];
    const float* Wg = (const float*)d_in[3];
    const float* bg = (const float*)d_in[4];
    float* out = (float*)d_out;

    cudaFuncSetAttribute(gemm_hmma, cudaFuncAttributeMaxDynamicSharedMemorySize,
                         SMEM_TOTAL);

    prep_all<<<PREP_TOTAL, 256>>>(U, V, X0, Wg);
    gemm_hmma<<<dim3(NEXP, B_ROWS / BM), 128, SMEM_TOTAL>>>();
    finalize<<<B_ROWS / 4, 256>>>(X0, bg, out);
}